// round 4
// baseline (speedup 1.0000x reference)
#include <cuda_runtime.h>
#include <cstdint>

// ---------------- problem constants (fixed shapes) ----------------
#define NNODES 10000
#define NEDGES 80000
#define BF     48          // B*S = 4*12
#define DD     32
#define NK     3
#define NHK    12          // H*K
#define NC     24          // 12 src scores + 12 dst scores
#define NROWS  (BF * NNODES)       // 480000
#define KDIM   (NHK * DD)          // 384
#define NTASKS (NNODES * (BF / 2)) // 240000 warp tasks

// ---------------- device scratch (static, allocation-free) ----------------
__device__ float g_S[(size_t)NROWS * NC];      // 46 MB  : per-row 24 scores
__device__ float g_AGG[(size_t)NROWS * KDIM];  // 737 MB : input-space aggregates
__device__ int   g_counts[NNODES];
__device__ int   g_off[NNODES + 1];
__device__ int   g_fill[NNODES];
__device__ int   g_eid[NEDGES];

// ---------------- packed f32x2 helpers (Blackwell) ----------------
__device__ __forceinline__ unsigned long long pk2(float x, float y) {
    unsigned long long r;
    asm("mov.b64 %0, {%1, %2};" : "=l"(r) : "f"(x), "f"(y));
    return r;
}
__device__ __forceinline__ void ffma2(unsigned long long& acc,
                                      unsigned long long a, unsigned long long b) {
    asm("fma.rn.f32x2 %0, %1, %2, %0;" : "+l"(acc) : "l"(a), "l"(b));
}
__device__ __forceinline__ float2 unpk2(unsigned long long v) {
    float lo, hi;
    asm("mov.b64 {%0, %1}, %2;" : "=f"(lo), "=f"(hi) : "l"(v));
    return make_float2(lo, hi);
}

// ---------------- K1: scores  S[row][c] = x[row] . wv[c]  (wv built per block) ----
__global__ void __launch_bounds__(256) k_scores(const float* __restrict__ x,
                                                const float* __restrict__ W,
                                                const float* __restrict__ a_src,
                                                const float* __restrict__ a_dst) {
    __shared__ float wv[NC * DD];
    for (int t = threadIdx.x; t < NC * DD; t += 256) {
        int c  = t >> 5;
        int i  = t & 31;
        int hk = (c < NHK) ? c : c - NHK;
        const float* av = (c < NHK) ? (a_src + (hk / NK) * DD) : (a_dst + (hk / NK) * DD);
        const float* wr = W + ((size_t)hk * DD + i) * DD;
        float s = 0.f;
#pragma unroll
        for (int j = 0; j < DD; j++) s = fmaf(wr[j], av[j], s);
        wv[c * DD + i] = s;
    }
    __syncthreads();
    int row = blockIdx.x * blockDim.x + threadIdx.x;
    if (row >= NROWS) return;
    const float4* xr = (const float4*)(x + (size_t)row * DD);
    float xv[DD];
#pragma unroll
    for (int q = 0; q < 8; q++) {
        float4 v = xr[q];
        xv[4 * q + 0] = v.x; xv[4 * q + 1] = v.y; xv[4 * q + 2] = v.z; xv[4 * q + 3] = v.w;
    }
    float* srow = g_S + (size_t)row * NC;
#pragma unroll
    for (int c = 0; c < NC; c++) {
        float s = 0.f;
#pragma unroll
        for (int i = 0; i < DD; i++) s = fmaf(xv[i], wv[c * DD + i], s);
        srow[c] = s;
    }
}

// ---------------- CSR build ----------------
__global__ void k_zero() {
    int t = blockIdx.x * blockDim.x + threadIdx.x;
    if (t < NNODES) { g_counts[t] = 0; g_fill[t] = 0; }
}
__global__ void k_hist(const int* __restrict__ dst) {
    int e = blockIdx.x * blockDim.x + threadIdx.x;
    if (e < NEDGES) atomicAdd(&g_counts[dst[e]], 1);
}
__global__ void k_scan() {   // 1 block, 1024 threads
    __shared__ int buf[1024];
    int tid = threadIdx.x;
    int carry = 0;
    for (int base = 0; base < NNODES; base += 1024) {
        int idx = base + tid;
        int v = (idx < NNODES) ? g_counts[idx] : 0;
        buf[tid] = v;
        __syncthreads();
        int incl = v;
#pragma unroll
        for (int d = 1; d < 1024; d <<= 1) {
            int t2 = (tid >= d) ? buf[tid - d] : 0;
            __syncthreads();
            incl += t2;
            buf[tid] = incl;
            __syncthreads();
        }
        if (idx < NNODES) g_off[idx] = carry + incl - v;
        carry += buf[1023];
        __syncthreads();
    }
    if (tid == 0) g_off[NNODES] = carry;
}
__global__ void k_scatter(const int* __restrict__ dst) {
    int e = blockIdx.x * blockDim.x + threadIdx.x;
    if (e < NEDGES) {
        int d = dst[e];
        int pos = g_off[d] + atomicAdd(&g_fill[d], 1);
        g_eid[pos] = e;
    }
}

// ---------------- K3: attention + input-space aggregation --------------------
// warp task (n, bp): batch rows b0=2*bp, b0+1.
// lanes 0..23 own (hk, b) softmax state; logits/exp cached in registers (<=16 edges).
__global__ void __launch_bounds__(256) k_attn(const float* __restrict__ x,
                                              const int*   __restrict__ src,
                                              const float* __restrict__ sup) {
    int lane   = threadIdx.x & 31;
    int warp0  = (blockIdx.x * blockDim.x + threadIdx.x) >> 5;
    int nwarps = (gridDim.x * blockDim.x) >> 5;
    int  hk    = lane % NHK;
    bool actA  = lane < 2 * NHK;
    int  kk    = hk % NK;
    int  qi    = lane & 15;
    int  bhalf = lane >> 4;
    int  sbase = bhalf * NHK;

    for (int task = warp0; task < NTASKS; task += nwarps) {
        int n  = task % NNODES;
        int bp = task / NNODES;
        int b0 = bp * 2;
        int p0 = g_off[n], p1 = g_off[n + 1];
        int deg = p1 - p0;

        int bA = b0 + ((lane < NHK) ? 0 : 1);
        const float* Sb = g_S + (size_t)bA * NNODES * NC + hk;
        float sd = actA ? Sb[(size_t)n * NC + NHK] : 0.f;

        // ---- pass A1: logits -> register cache + max ----
        float m = -1e30f;
        float lc[16];
#pragma unroll
        for (int i = 0; i < 16; i++) {
            if (i >= deg) break;
            int e = g_eid[p0 + i];
            int s = __ldg(&src[e]);
            float l = 0.f;
            if (actA) {
                l = Sb[(size_t)s * NC] + sd;
                l = (l > 0.f) ? l : 0.2f * l;
                m = fmaxf(m, l);
            }
            lc[i] = l;
        }
        for (int i = 16; i < deg; i++) {          // rare overflow
            int e = g_eid[p0 + i];
            int s = __ldg(&src[e]);
            if (actA) {
                float l = Sb[(size_t)s * NC] + sd;
                l = (l > 0.f) ? l : 0.2f * l;
                m = fmaxf(m, l);
            }
        }
        // ---- pass A2: exp in registers + denom ----
        float den = 0.f;
#pragma unroll
        for (int i = 0; i < 16; i++) {
            if (i >= deg) break;
            float ex = __expf(lc[i] - m);
            lc[i] = ex;
            den += ex;
        }
        for (int i = 16; i < deg; i++) {
            int e = g_eid[p0 + i];
            int s = __ldg(&src[e]);
            if (actA) {
                float l = Sb[(size_t)s * NC] + sd;
                l = (l > 0.f) ? l : 0.2f * l;
                den += __expf(l - m);
            }
        }
        float invden = 1.f / (den + 1e-9f);

        // ---- pass B: alpha * support weighted aggregation of x[src] ----
        int bB = b0 + bhalf;
        const float* xb = x + (size_t)bB * NNODES * DD + 2 * qi;
        float2 agg[NHK];
#pragma unroll
        for (int j = 0; j < NHK; j++) agg[j] = make_float2(0.f, 0.f);

#pragma unroll
        for (int i = 0; i < 16; i++) {
            if (i >= deg) break;
            int e = g_eid[p0 + i];
            int s = __ldg(&src[e]);
            float a = actA ? lc[i] * invden * __ldg(&sup[kk * NEDGES + e]) : 0.f;
            float2 xv = *(const float2*)(xb + (size_t)s * DD);
#pragma unroll
            for (int j = 0; j < NHK; j++) {
                float aj = __shfl_sync(0xffffffffu, a, sbase + j);
                agg[j].x = fmaf(aj, xv.x, agg[j].x);
                agg[j].y = fmaf(aj, xv.y, agg[j].y);
            }
        }
        for (int i = 16; i < deg; i++) {          // rare overflow: recompute
            int e = g_eid[p0 + i];
            int s = __ldg(&src[e]);
            float a = 0.f;
            if (actA) {
                float l = Sb[(size_t)s * NC] + sd;
                l = (l > 0.f) ? l : 0.2f * l;
                a = __expf(l - m) * invden * __ldg(&sup[kk * NEDGES + e]);
            }
            float2 xv = *(const float2*)(xb + (size_t)s * DD);
#pragma unroll
            for (int j = 0; j < NHK; j++) {
                float aj = __shfl_sync(0xffffffffu, a, sbase + j);
                agg[j].x = fmaf(aj, xv.x, agg[j].x);
                agg[j].y = fmaf(aj, xv.y, agg[j].y);
            }
        }
        float* arow = g_AGG + ((size_t)bB * NNODES + n) * KDIM + 2 * qi;
#pragma unroll
        for (int j = 0; j < NHK; j++) __stcs((float2*)(arow + j * DD), agg[j]);
    }
}

// ---------------- K4: out = relu( (AGG @ Wstack)/H + x ) ----------------------
// Warp-tile = 32 rows x 32 cols; lane owns col c = lane.
// W pairs in registers per 32-k chunk (amortized over 32 rows);
// A staged to smem per warp, read via LDS.128 broadcast (1 cyc -> 2 FFMA2).
#define GT_ROWS 32
#define GW      8
#define AS_LD   36   // padded row (floats): 144B, 16B-aligned, conflict-free
__global__ void __launch_bounds__(256, 1) k_gemm2(const float* __restrict__ Wg,
                                                  const float* __restrict__ x,
                                                  float* __restrict__ out) {
    extern __shared__ char smem[];
    unsigned long long* Wp = (unsigned long long*)smem;          // [12][16][32] u64
    float* As = (float*)(smem + NHK * 16 * 32 * 8);              // [GW][32][AS_LD]

    int tid = threadIdx.x, lane = tid & 31, w = tid >> 5;
    // build packed W: Wp[hk][q][c] = (W[hk][2q][c], W[hk][2q+1][c])
    for (int idx = tid; idx < NHK * 16 * 32; idx += 256) {
        int hk = idx >> 9, q = (idx >> 5) & 15, c = idx & 31;
        float lo = Wg[hk * 1024 + (2 * q) * 32 + c];
        float hi = Wg[hk * 1024 + (2 * q + 1) * 32 + c];
        Wp[idx] = pk2(lo, hi);
    }
    __syncthreads();

    size_t row0 = ((size_t)blockIdx.x * GW + w) * GT_ROWS;
    float* myAs = As + w * (GT_ROWS * AS_LD);
    int rsub = lane >> 3;        // 0..3
    int qsub = lane & 7;         // 0..7

    unsigned long long acc[GT_ROWS];
#pragma unroll
    for (int r = 0; r < GT_ROWS; r++) acc[r] = 0ull;

    // software pipeline: prefetch chunk 0 (coalesced: 4 rows per LDG.128)
    float4 v[8];
#pragma unroll
    for (int i = 0; i < 8; i++)
        v[i] = __ldcs((const float4*)(g_AGG + (row0 + i * 4 + rsub) * KDIM + qsub * 4));

    for (int hk = 0; hk < NHK; hk++) {
        // stage current chunk to smem
#pragma unroll
        for (int i = 0; i < 8; i++)
            *(float4*)(myAs + (i * 4 + rsub) * AS_LD + qsub * 4) = v[i];
        // W pair registers for this chunk
        unsigned long long wreg[16];
#pragma unroll
        for (int q = 0; q < 16; q++) wreg[q] = Wp[(hk * 16 + q) * 32 + lane];
        __syncwarp();
        // prefetch next chunk while computing
        if (hk < NHK - 1) {
#pragma unroll
            for (int i = 0; i < 8; i++)
                v[i] = __ldcs((const float4*)(g_AGG + (row0 + i * 4 + rsub) * KDIM
                                              + (hk + 1) * 32 + qsub * 4));
        }
        // compute: 32 rows x 8 LDS.128-broadcast x 2 FFMA2
#pragma unroll
        for (int r = 0; r < GT_ROWS; r++) {
#pragma unroll
            for (int q2 = 0; q2 < 8; q2++) {
                float4 a4 = *(const float4*)(myAs + r * AS_LD + q2 * 4);
                ffma2(acc[r], pk2(a4.x, a4.y), wreg[2 * q2]);
                ffma2(acc[r], pk2(a4.z, a4.w), wreg[2 * q2 + 1]);
            }
        }
        __syncwarp();
    }
    // epilogue: horizontal add, /H, residual, relu
#pragma unroll
    for (int r = 0; r < GT_ROWS; r++) {
        float2 p = unpk2(acc[r]);
        size_t o = (row0 + r) * DD + lane;
        out[o] = fmaxf(fmaf(p.x + p.y, 0.25f, x[o]), 0.f);
    }
}

// ---------------- launch ----------------
extern "C" void kernel_launch(void* const* d_in, const int* in_sizes, int n_in,
                              void* d_out, int out_size) {
    const float* x   = (const float*)d_in[0];   // [48,10000,32]
    const int*   src = (const int*)  d_in[1];   // [E]
    const int*   dst = (const int*)  d_in[2];   // [E]
    const float* sup = (const float*)d_in[3];   // [3,E]
    const float* W   = (const float*)d_in[4];   // [4,3,32,32]
    const float* a_s = (const float*)d_in[5];   // [4,32]
    const float* a_d = (const float*)d_in[6];   // [4,32]
    float*       out = (float*)d_out;

    k_scores<<<(NROWS + 255) / 256, 256>>>(x, W, a_s, a_d);
    k_zero<<<(NNODES + 255) / 256, 256>>>();
    k_hist<<<(NEDGES + 255) / 256, 256>>>(dst);
    k_scan<<<1, 1024>>>();
    k_scatter<<<(NEDGES + 255) / 256, 256>>>(dst);
    k_attn<<<1184, 256>>>(x, src, sup);

    int smem = NHK * 16 * 32 * 8 + GW * GT_ROWS * AS_LD * 4;   // 49152 + 36864 = 86016
    cudaFuncSetAttribute(k_gemm2, cudaFuncAttributeMaxDynamicSharedMemorySize, smem);
    k_gemm2<<<NROWS / (GT_ROWS * GW), 256, smem>>>(W, x, out);
}